// round 7
// baseline (speedup 1.0000x reference)
#include <cuda_runtime.h>

// Problem constants (fixed by setup_inputs)
#define B_  8
#define C_  24
#define H_  320
#define W_  640
#define HW_ (H_ * W_)            // 204800
#define PLANE2_ (HW_ / 2)        // 102400 float2 groups per image plane
#define NPIX2_ (B_ * PLANE2_)    // 819200 total float2 groups
#define NBHW_ (B_ * HW_)         // pred element count / prob plane base

#define CHUNK_ 4                 // channels per load batch (24 = 6 * 4)
#define THREADS_ 256

__global__ __launch_bounds__(THREADS_, 6)
void sparse_regression_f2b_kernel(const float* __restrict__ cost,
                                  const float* __restrict__ disp,
                                  float* __restrict__ out)
{
    int p = blockIdx.x * THREADS_ + threadIdx.x;
    if (p >= NPIX2_) return;

    int b = p / PLANE2_;
    int r = p - b * PLANE2_;                 // float2 index within plane
    int base2 = b * (C_ * PLANE2_) + r;      // < 19.7M, fits int

    const float2* cbase = reinterpret_cast<const float2*>(cost) + base2;
    const float2* dbase = reinterpret_cast<const float2*>(disp) + base2;

    // running top-2 (value, disparity) per lane (2 lanes)
    float v0[2], v1[2], d0[2], d1[2];
    #pragma unroll
    for (int l = 0; l < 2; ++l) {
        v0[l] = -3.4e38f; d0[l] = 0.0f;
        v1[l] = -3.4e38f; d1[l] = 0.0f;
    }

    #pragma unroll
    for (int ch = 0; ch < C_; ch += CHUNK_) {
        // ---- batched loads: 8 LDG.64 issued before any consume ----
        float2 creg[CHUNK_], dreg[CHUNK_];
        #pragma unroll
        for (int j = 0; j < CHUNK_; ++j) {
            int off = (ch + j) * PLANE2_;
            creg[j] = __ldcs(cbase + off);
            dreg[j] = __ldcs(dbase + off);
        }
        // ---- consume ----
        #pragma unroll
        for (int j = 0; j < CHUNK_; ++j) {
            float cv[2] = {creg[j].x, creg[j].y};
            float dv[2] = {dreg[j].x, dreg[j].y};
            #pragma unroll
            for (int l = 0; l < 2; ++l) {
                float v = cv[l];
                float d = dv[l];
                if (v > v0[l]) {
                    v1[l] = v0[l]; d1[l] = d0[l];
                    v0[l] = v;     d0[l] = d;
                } else if (v > v1[l]) {
                    v1[l] = v;     d1[l] = d;
                }
            }
        }
    }

    // 2-way softmax (v1 <= v0, so e in (0,1]) and weighted disparity
    float pred[2], pr0[2], pr1[2];
    #pragma unroll
    for (int l = 0; l < 2; ++l) {
        float e   = __expf(v1[l] - v0[l]);
        float inv = 1.0f / (1.0f + e);
        float p0  = inv;
        float p1  = e * inv;
        pr0[l] = p0;
        pr1[l] = p1;
        pred[l] = d0[l] * p0 + d1[l] * p1;
    }

    int po = b * PLANE2_ + r;   // in float2 units
    __stcs(reinterpret_cast<float2*>(out) + po, make_float2(pred[0], pred[1]));

    // prob [B, 2, H, W] after pred [B, H, W]  (float2 units)
    int q0 = (NBHW_ / 2) + (b * 2 + 0) * PLANE2_ + r;
    int q1 = (NBHW_ / 2) + (b * 2 + 1) * PLANE2_ + r;
    __stcs(reinterpret_cast<float2*>(out) + q0, make_float2(pr0[0], pr0[1]));
    __stcs(reinterpret_cast<float2*>(out) + q1, make_float2(pr1[0], pr1[1]));
}

extern "C" void kernel_launch(void* const* d_in, const int* in_sizes, int n_in,
                              void* d_out, int out_size)
{
    const float* cost = (const float*)d_in[0];
    const float* disp = (const float*)d_in[1];
    float* out = (float*)d_out;

    const int blocks = (NPIX2_ + THREADS_ - 1) / THREADS_;   // 3200
    sparse_regression_f2b_kernel<<<blocks, THREADS_>>>(cost, disp, out);
}

// round 8
// speedup vs baseline: 1.0447x; 1.0447x over previous
#include <cuda_runtime.h>

// Problem constants (fixed by setup_inputs)
#define B_  8
#define C_  24
#define H_  320
#define W_  640
#define HW_ (H_ * W_)            // 204800
#define PLANE2_ (HW_ / 2)        // 102400 float2 groups per image plane
#define NPIX2_ (B_ * PLANE2_)    // 819200 total float2 groups
#define NBHW_ (B_ * HW_)         // pred element count / prob plane base

#define CHUNK_ 8                 // channels per load batch (24 = 3 * 8)
#define THREADS_ 256

__global__ __launch_bounds__(THREADS_)
void sparse_regression_f2c_kernel(const float* __restrict__ cost,
                                  const float* __restrict__ disp,
                                  float* __restrict__ out)
{
    int p = blockIdx.x * THREADS_ + threadIdx.x;
    if (p >= NPIX2_) return;

    int b = p / PLANE2_;
    int r = p - b * PLANE2_;                 // float2 index within plane
    int base2 = b * (C_ * PLANE2_) + r;      // < 19.7M, fits int

    const float2* cbase = reinterpret_cast<const float2*>(cost) + base2;
    const float2* dbase = reinterpret_cast<const float2*>(disp) + base2;

    // running top-2 (value, disparity) per lane (2 lanes)
    float v0[2], v1[2], d0[2], d1[2];
    #pragma unroll
    for (int l = 0; l < 2; ++l) {
        v0[l] = -3.4e38f; d0[l] = 0.0f;
        v1[l] = -3.4e38f; d1[l] = 0.0f;
    }

    #pragma unroll
    for (int ch = 0; ch < C_; ch += CHUNK_) {
        // ---- batched loads: 16 LDG.64 issued before any consume ----
        float2 creg[CHUNK_], dreg[CHUNK_];
        #pragma unroll
        for (int j = 0; j < CHUNK_; ++j) {
            int off = (ch + j) * PLANE2_;
            creg[j] = __ldcs(cbase + off);
            dreg[j] = __ldcs(dbase + off);
        }
        // ---- consume ----
        #pragma unroll
        for (int j = 0; j < CHUNK_; ++j) {
            float cv[2] = {creg[j].x, creg[j].y};
            float dv[2] = {dreg[j].x, dreg[j].y};
            #pragma unroll
            for (int l = 0; l < 2; ++l) {
                float v = cv[l];
                float d = dv[l];
                if (v > v0[l]) {
                    v1[l] = v0[l]; d1[l] = d0[l];
                    v0[l] = v;     d0[l] = d;
                } else if (v > v1[l]) {
                    v1[l] = v;     d1[l] = d;
                }
            }
        }
    }

    // 2-way softmax (v1 <= v0, so e in (0,1]) and weighted disparity
    float pred[2], pr0[2], pr1[2];
    #pragma unroll
    for (int l = 0; l < 2; ++l) {
        float e   = __expf(v1[l] - v0[l]);
        float inv = 1.0f / (1.0f + e);
        float p0  = inv;
        float p1  = e * inv;
        pr0[l] = p0;
        pr1[l] = p1;
        pred[l] = d0[l] * p0 + d1[l] * p1;
    }

    int po = b * PLANE2_ + r;   // in float2 units
    __stcs(reinterpret_cast<float2*>(out) + po, make_float2(pred[0], pred[1]));

    // prob [B, 2, H, W] after pred [B, H, W]  (float2 units)
    int q0 = (NBHW_ / 2) + (b * 2 + 0) * PLANE2_ + r;
    int q1 = (NBHW_ / 2) + (b * 2 + 1) * PLANE2_ + r;
    __stcs(reinterpret_cast<float2*>(out) + q0, make_float2(pr0[0], pr0[1]));
    __stcs(reinterpret_cast<float2*>(out) + q1, make_float2(pr1[0], pr1[1]));
}

extern "C" void kernel_launch(void* const* d_in, const int* in_sizes, int n_in,
                              void* d_out, int out_size)
{
    const float* cost = (const float*)d_in[0];
    const float* disp = (const float*)d_in[1];
    float* out = (float*)d_out;

    const int blocks = (NPIX2_ + THREADS_ - 1) / THREADS_;   // 3200
    sparse_regression_f2c_kernel<<<blocks, THREADS_>>>(cost, disp, out);
}

// round 9
// speedup vs baseline: 1.1242x; 1.0761x over previous
#include <cuda_runtime.h>

// Problem constants (fixed by setup_inputs)
#define B_  8
#define C_  24
#define H_  320
#define W_  640
#define HW_ (H_ * W_)            // 204800
#define PLANE2_ (HW_ / 2)        // 102400 float2 groups per image plane
#define NPIX2_ (B_ * PLANE2_)    // 819200 total float2 groups
#define NBHW_ (B_ * HW_)         // pred element count / prob plane base

#define CHUNK_ 8                 // channels per load batch (24 = 3 * 8)
#define THREADS_ 128

__global__ __launch_bounds__(THREADS_)
void sparse_regression_f2d_kernel(const float* __restrict__ cost,
                                  const float* __restrict__ disp,
                                  float* __restrict__ out)
{
    int p = blockIdx.x * THREADS_ + threadIdx.x;
    if (p >= NPIX2_) return;

    int b = p / PLANE2_;
    int r = p - b * PLANE2_;                 // float2 index within plane
    int base2 = b * (C_ * PLANE2_) + r;      // < 19.7M, fits int

    const float2* cbase = reinterpret_cast<const float2*>(cost) + base2;
    const float2* dbase = reinterpret_cast<const float2*>(disp) + base2;

    // running top-2 (value, disparity) per lane (2 lanes)
    float v0[2], v1[2], d0[2], d1[2];
    #pragma unroll
    for (int l = 0; l < 2; ++l) {
        v0[l] = -3.4e38f; d0[l] = 0.0f;
        v1[l] = -3.4e38f; d1[l] = 0.0f;
    }

    #pragma unroll
    for (int ch = 0; ch < C_; ch += CHUNK_) {
        // ---- batched loads: 16 LDG.64 issued before any consume ----
        float2 creg[CHUNK_], dreg[CHUNK_];
        #pragma unroll
        for (int j = 0; j < CHUNK_; ++j) {
            int off = (ch + j) * PLANE2_;
            creg[j] = __ldcs(cbase + off);
            dreg[j] = __ldcs(dbase + off);
        }
        // ---- consume ----
        #pragma unroll
        for (int j = 0; j < CHUNK_; ++j) {
            float cv[2] = {creg[j].x, creg[j].y};
            float dv[2] = {dreg[j].x, dreg[j].y};
            #pragma unroll
            for (int l = 0; l < 2; ++l) {
                float v = cv[l];
                float d = dv[l];
                if (v > v0[l]) {
                    v1[l] = v0[l]; d1[l] = d0[l];
                    v0[l] = v;     d0[l] = d;
                } else if (v > v1[l]) {
                    v1[l] = v;     d1[l] = d;
                }
            }
        }
    }

    // 2-way softmax (v1 <= v0, so e in (0,1]) and weighted disparity
    float pred[2], pr0[2], pr1[2];
    #pragma unroll
    for (int l = 0; l < 2; ++l) {
        float e   = __expf(v1[l] - v0[l]);
        float inv = 1.0f / (1.0f + e);
        float p0  = inv;
        float p1  = e * inv;
        pr0[l] = p0;
        pr1[l] = p1;
        pred[l] = d0[l] * p0 + d1[l] * p1;
    }

    int po = b * PLANE2_ + r;   // in float2 units
    __stcs(reinterpret_cast<float2*>(out) + po, make_float2(pred[0], pred[1]));

    // prob [B, 2, H, W] after pred [B, H, W]  (float2 units)
    int q0 = (NBHW_ / 2) + (b * 2 + 0) * PLANE2_ + r;
    int q1 = (NBHW_ / 2) + (b * 2 + 1) * PLANE2_ + r;
    __stcs(reinterpret_cast<float2*>(out) + q0, make_float2(pr0[0], pr0[1]));
    __stcs(reinterpret_cast<float2*>(out) + q1, make_float2(pr1[0], pr1[1]));
}

extern "C" void kernel_launch(void* const* d_in, const int* in_sizes, int n_in,
                              void* d_out, int out_size)
{
    const float* cost = (const float*)d_in[0];
    const float* disp = (const float*)d_in[1];
    float* out = (float*)d_out;

    const int blocks = (NPIX2_ + THREADS_ - 1) / THREADS_;   // 6400
    sparse_regression_f2d_kernel<<<blocks, THREADS_>>>(cost, disp, out);
}